// round 14
// baseline (speedup 1.0000x reference)
#include <cuda_runtime.h>
#include <cuda_fp16.h>
#include <cstdint>
#include <cstddef>

#define N_ATOMS 262144
#define BATCH   4096
#define HIDDEN  256
#define SCALE   0.125f
#define LN_EPS  1e-5f
#define SM_EPS  1e-16f

#define NTILES  (N_ATOMS / 128)     // 2048 tiles of 128 rows
#define NCTAS   148
#define APITCH  264                 // halves; 528B row = 4 banks mod 32
#define BPITCH  72                  // halves; 144B row = 4 banks mod 32
#define BCHUNKB (256 * BPITCH * 2)  // 36864 bytes per k64 chunk

// ---------------- scratch (device globals, no allocation) ----------------
__device__ float    g_A[HIDDEN * HIDDEN];   // A = Wq @ Wk^T
__device__ float    g_dvec[HIDDEN];
__device__ float    g_vq[HIDDEN];
__device__ float    g_cconst[1];
__device__ float    g_U[BATCH * HIDDEN];
__device__ float    g_c[BATCH];
__device__ float    g_e[N_ATOMS];           // exp(dots) directly (no max pass)
__device__ float    g_segsum[BATCH];
__device__ __half   g_WvT16[HIDDEN * HIDDEN];           // WvT16[n][k] = fp16(Wv[k][n])
__device__ __half   g_drug16[(size_t)N_ATOMS * HIDDEN]; // fp16 copy of drug

// ---------------- K0: A = Wq @ Wk^T, vq/dvec/cconst, segsum zero, Wv transpose
__global__ void k_pre(const float* __restrict__ Wq, const float* __restrict__ bq,
                      const float* __restrict__ Wk, const float* __restrict__ bk,
                      const float* __restrict__ Wv) {
    int t = threadIdx.x;
    if (blockIdx.x < 32) {
        __shared__ float wq[8][HIDDEN];
        int k0 = blockIdx.x * 8;
        #pragma unroll
        for (int e = 0; e < 8; e++) wq[e][t] = Wq[(k0 + e) * HIDDEN + t];
        __syncthreads();
        float acc[8];
        #pragma unroll
        for (int r = 0; r < 8; r++) acc[r] = 0.f;
        for (int j = 0; j < HIDDEN; j++) {
            float w = __ldg(&Wk[t * HIDDEN + j]);
            #pragma unroll
            for (int r = 0; r < 8; r++) acc[r] += wq[r][j] * w;
        }
        #pragma unroll
        for (int r = 0; r < 8; r++) g_A[(k0 + r) * HIDDEN + t] = acc[r];
    } else if (blockIdx.x == 32) {
        for (int i = t; i < BATCH; i += 256) g_segsum[i] = 0.f;
        __shared__ float bqs[HIDDEN], bks[HIDDEN];
        bqs[t] = bq[t]; bks[t] = bk[t];
        __syncthreads();
        float v = 0.f, d = 0.f;
        for (int j = 0; j < HIDDEN; j++) {
            v += __ldg(&Wq[t * HIDDEN + j]) * bks[j];
            d += __ldg(&Wk[t * HIDDEN + j]) * bqs[j];
        }
        g_vq[t] = v; g_dvec[t] = d;
        if (t == 0) {
            float c = 0.f;
            for (int j = 0; j < HIDDEN; j++) c += bqs[j] * bks[j];
            g_cconst[0] = c;
        }
    } else {
        __shared__ float ts[32][33];
        int n0 = (blockIdx.x - 33) * 32;
        int tx = t & 31, ty = t >> 5;              // 32 x 8
        for (int kb = 0; kb < 8; kb++) {
            int k0 = kb * 32;
            #pragma unroll
            for (int j = 0; j < 32; j += 8)
                ts[ty + j][tx] = Wv[(size_t)(k0 + ty + j) * HIDDEN + n0 + tx];
            __syncthreads();
            #pragma unroll
            for (int j = 0; j < 32; j += 8)
                g_WvT16[(size_t)(n0 + ty + j) * HIDDEN + k0 + tx] =
                    __float2half_rn(ts[tx][ty + j]);
            __syncthreads();
        }
    }
}

// ---------------- K1: U = protein @ A + d ; c = protein @ vq + cc ----------------
__global__ void k_u(const float* __restrict__ P) {
    __shared__ float ps[HIDDEN][16];
    __shared__ float vqs[HIDDEN];
    int t = threadIdx.x;
    int b0 = blockIdx.x * 16;
    #pragma unroll
    for (int e = 0; e < 16; e++) ps[t][e] = P[(b0 + e) * HIDDEN + t];
    vqs[t] = g_vq[t];
    __syncthreads();
    float acc[16];
    #pragma unroll
    for (int r = 0; r < 16; r++) acc[r] = 0.f;
    for (int k = 0; k < HIDDEN; k++) {
        float a = g_A[k * HIDDEN + t];
        const float4* p4 = (const float4*)ps[k];
        float4 x0 = p4[0], x1 = p4[1], x2 = p4[2], x3 = p4[3];
        acc[0]  += x0.x * a; acc[1]  += x0.y * a; acc[2]  += x0.z * a; acc[3]  += x0.w * a;
        acc[4]  += x1.x * a; acc[5]  += x1.y * a; acc[6]  += x1.z * a; acc[7]  += x1.w * a;
        acc[8]  += x2.x * a; acc[9]  += x2.y * a; acc[10] += x2.z * a; acc[11] += x2.w * a;
        acc[12] += x3.x * a; acc[13] += x3.y * a; acc[14] += x3.z * a; acc[15] += x3.w * a;
    }
    float dv = g_dvec[t];
    #pragma unroll
    for (int r = 0; r < 16; r++) g_U[(b0 + r) * HIDDEN + t] = acc[r] + dv;
    if (t < 16) {
        float s = 0.f;
        for (int k = 0; k < HIDDEN; k++) s += ps[k][t] * vqs[k];
        g_c[b0 + t] = s + g_cconst[0];
    }
}

// ---------------- K2: dots -> exp -> segment sum + drug->fp16 ---------------
__device__ __forceinline__ unsigned pack2(float a, float b) {
    __half2 h = __float22half2_rn(make_float2(a, b));
    return *(unsigned*)&h;
}

__global__ void k_dots(const float* __restrict__ drug, const int* __restrict__ bidx) {
    int warp = threadIdx.x >> 5, lane = threadIdx.x & 31;
    int i0 = (blockIdx.x * 8 + warp) * 2;
    int b0 = bidx[i0], b1 = bidx[i0 + 1];
    const float4* d0 = (const float4*)(drug + (size_t)i0 * HIDDEN);
    const float4* d1 = (const float4*)(drug + (size_t)(i0 + 1) * HIDDEN);
    const float4* u0 = (const float4*)(g_U + (size_t)b0 * HIDDEN);
    const float4* u1 = (const float4*)(g_U + (size_t)b1 * HIDDEN);
    float4 x0 = d0[lane * 2], x1 = d0[lane * 2 + 1];
    float4 x2 = d1[lane * 2], x3 = d1[lane * 2 + 1];
    float4 y0 = u0[lane * 2], y1 = u0[lane * 2 + 1];
    float4 y2 = u1[lane * 2], y3 = u1[lane * 2 + 1];

    uint4 p0 = make_uint4(pack2(x0.x, x0.y), pack2(x0.z, x0.w),
                          pack2(x1.x, x1.y), pack2(x1.z, x1.w));
    uint4 p1 = make_uint4(pack2(x2.x, x2.y), pack2(x2.z, x2.w),
                          pack2(x3.x, x3.y), pack2(x3.z, x3.w));
    *(uint4*)(g_drug16 + (size_t)i0 * HIDDEN + lane * 8) = p0;
    *(uint4*)(g_drug16 + (size_t)(i0 + 1) * HIDDEN + lane * 8) = p1;

    float s0 = x0.x * y0.x + x0.y * y0.y + x0.z * y0.z + x0.w * y0.w
             + x1.x * y1.x + x1.y * y1.y + x1.z * y1.z + x1.w * y1.w;
    float s1 = x2.x * y2.x + x2.y * y2.y + x2.z * y2.z + x2.w * y2.w
             + x3.x * y3.x + x3.y * y3.y + x3.z * y3.z + x3.w * y3.w;
    #pragma unroll
    for (int off = 16; off > 0; off >>= 1) {
        s0 += __shfl_xor_sync(0xFFFFFFFFu, s0, off);
        s1 += __shfl_xor_sync(0xFFFFFFFFu, s1, off);
    }
    if (lane == 0) {
        float e0 = expf((s0 + g_c[b0]) * SCALE);
        float e1 = expf((s1 + g_c[b1]) * SCALE);
        g_e[i0]     = e0;
        g_e[i0 + 1] = e1;
        atomicAdd(&g_segsum[b0], e0);
        atomicAdd(&g_segsum[b1], e1);
    }
}

// ---------------- K3: persistent fp16-mma V-GEMM — 1024 threads, 4x8 warps ----
// grid=148, 1024 threads (8 warps/SMSP, occ 50%). M=128 tiles, B resident,
// A single-buffered. Warp tile M32 x N32: acc=32 regs -> <=64 regs/thread.
// Same 2-barrier tile structure as R11; latency hidden by TLP, epilogue
// per-thread work halved.

struct alignas(16) Sm {
    __half a[128 * APITCH];            //  67,584 B
    __half b[4][256 * BPITCH];         // 147,456 B
    float  attn[128];
    float  bvv[HIDDEN], gm[HIDDEN], bt[HIDDEN];
    float  rs[8][128], rq[8][128];     //   8,192 B
};

__device__ __forceinline__ void cp16(void* s, const void* g) {
    unsigned sa = (unsigned)__cvta_generic_to_shared(s);
    asm volatile("cp.async.cg.shared.global [%0], [%1], 16;" :: "r"(sa), "l"(g));
}
__device__ __forceinline__ void ldsm4(unsigned* r, unsigned addr) {
    asm volatile("ldmatrix.sync.aligned.m8n8.x4.shared.b16 {%0,%1,%2,%3}, [%4];"
        : "=r"(r[0]), "=r"(r[1]), "=r"(r[2]), "=r"(r[3]) : "r"(addr));
}
__device__ __forceinline__ void mma16(float* c, const unsigned* a, const unsigned* b) {
    asm volatile(
        "mma.sync.aligned.m16n8k16.row.col.f32.f16.f16.f32 "
        "{%0,%1,%2,%3},{%4,%5,%6,%7},{%8,%9},{%0,%1,%2,%3};"
        : "+f"(c[0]), "+f"(c[1]), "+f"(c[2]), "+f"(c[3])
        : "r"(a[0]), "r"(a[1]), "r"(a[2]), "r"(a[3]), "r"(b[0]), "r"(b[1]));
}

__device__ __forceinline__ void loadA(__half* dst, int tile, int t) {
    const __half* src = g_drug16 + (size_t)tile * 128 * HIDDEN;
    #pragma unroll
    for (int e = 0; e < 4; e++) {
        int idx = e * 1024 + t;         // 4096 chunks of 8 halves
        int r = idx >> 5, j = idx & 31;
        cp16(dst + r * APITCH + j * 8, src + r * HIDDEN + j * 8);
    }
}
__device__ __forceinline__ void loadB(__half* dst, int c, int t) {
    const __half* src = g_WvT16 + c * 64;
    #pragma unroll
    for (int e = 0; e < 2; e++) {
        int idx = e * 1024 + t;         // 2048 chunks of 8 halves
        int n = idx >> 3, j = idx & 7;
        cp16(dst + n * BPITCH + j * 8, src + n * HIDDEN + j * 8);
    }
}
#define COMMIT() asm volatile("cp.async.commit_group;")
#define WAITG(n) asm volatile("cp.async.wait_group %0;" :: "n"(n) : "memory")

__global__ void __launch_bounds__(1024, 1) k_main(
    const float* __restrict__ bv, const float* __restrict__ gamma,
    const float* __restrict__ beta, const int* __restrict__ bidx,
    float* __restrict__ out, float* __restrict__ attn_out)
{
    extern __shared__ char smem_raw[];
    Sm& sm = *(Sm*)smem_raw;
    int t = threadIdx.x;
    int w = t >> 5, lane = t & 31;
    int g = lane >> 2, tig = lane & 3;
    int wm = w >> 3, wn = w & 7;       // 4x8 warps: M32 x N32 each

    // one-time: B resident + first A + constants; attn(tile0) into a register
    int tl = blockIdx.x;
    #pragma unroll
    for (int c = 0; c < 4; c++) loadB(sm.b[c], c, t);
    loadA(sm.a, tl, t);
    COMMIT();
    if (t < 256) { sm.bvv[t] = bv[t]; sm.gm[t] = gamma[t]; sm.bt[t] = beta[t]; }

    float attnReg = 0.f;
    if (t < 128) {
        int i = tl * 128 + t;
        attnReg = g_e[i] / (g_segsum[bidx[i]] + SM_EPS);
    }

    unsigned aBase = (unsigned)__cvta_generic_to_shared(sm.a);
    unsigned bBase = (unsigned)__cvta_generic_to_shared(sm.b[0]);
    unsigned aLane = aBase + (unsigned)((wm * 32 + (lane & 15)) * APITCH * 2
                                        + ((lane >> 4) << 3) * 2);
    unsigned bRow  = bBase + (unsigned)((wn * 32 + ((lane >> 4) << 3) + (lane & 7)) * BPITCH * 2)
                   + (unsigned)((((lane >> 3) & 1) << 3) * 2);

    for (; tl < NTILES; tl += NCTAS) {
        int rb = tl * 128;
        int nxt = tl + NCTAS;

        WAITG(0);                       // current A complete
        if (t < 128) {
            sm.attn[t] = attnReg;
            if (attn_out) attn_out[rb + t] = attnReg;
        }
        __syncthreads();                // A + attn visible

        // ---- mma burst: simple in-order, TLP hides latency
        float acc[2][4][4];
        #pragma unroll
        for (int mt = 0; mt < 2; mt++)
            #pragma unroll
            for (int nt = 0; nt < 4; nt++)
                #pragma unroll
                for (int q = 0; q < 4; q++) acc[mt][nt][q] = 0.f;

        #pragma unroll
        for (int k16 = 0; k16 < 16; k16++) {
            unsigned a0[4], a1[4];
            ldsm4(a0, aLane + (unsigned)(k16 * 32));
            ldsm4(a1, aLane + (unsigned)(16 * APITCH * 2 + k16 * 32));
            unsigned bC = bRow + (unsigned)((k16 >> 2) * BCHUNKB + (k16 & 3) * 32);
            #pragma unroll
            for (int p = 0; p < 2; p++) {
                unsigned bq[4];
                ldsm4(bq, bC + (unsigned)(p * 16 * BPITCH * 2));
                mma16(acc[0][2 * p],     a0, &bq[0]);
                mma16(acc[1][2 * p],     a1, &bq[0]);
                mma16(acc[0][2 * p + 1], a0, &bq[2]);
                mma16(acc[1][2 * p + 1], a1, &bq[2]);
            }
        }

        // ---- fold: v = attn*(acc+bv) + residual(sm.a)  (all sm.a reads here)
        float rsum[2][2], rsq[2][2];
        #pragma unroll
        for (int mt = 0; mt < 2; mt++) { rsum[mt][0] = rsum[mt][1] = 0.f;
                                         rsq[mt][0] = rsq[mt][1] = 0.f; }
        #pragma unroll
        for (int mt = 0; mt < 2; mt++) {
            int r0 = wm * 32 + mt * 16 + g, r1 = r0 + 8;
            float a0 = sm.attn[r0], a1 = sm.attn[r1];
            #pragma unroll
            for (int nt = 0; nt < 4; nt++) {
                int c0 = wn * 32 + nt * 8 + 2 * tig;
                float2 q0 = __half22float2(*(const __half2*)&sm.a[r0 * APITCH + c0]);
                float2 q1 = __half22float2(*(const __half2*)&sm.a[r1 * APITCH + c0]);
                float bv0 = sm.bvv[c0], bv1 = sm.bvv[c0 + 1];
                float v0 = fmaf(a0, acc[mt][nt][0] + bv0, q0.x);
                float v1 = fmaf(a0, acc[mt][nt][1] + bv1, q0.y);
                float v2 = fmaf(a1, acc[mt][nt][2] + bv0, q1.x);
                float v3 = fmaf(a1, acc[mt][nt][3] + bv1, q1.y);
                acc[mt][nt][0] = v0; acc[mt][nt][1] = v1;
                acc[mt][nt][2] = v2; acc[mt][nt][3] = v3;
                rsum[mt][0] += v0 + v1;  rsq[mt][0] += v0 * v0 + v1 * v1;
                rsum[mt][1] += v2 + v3;  rsq[mt][1] += v2 * v2 + v3 * v3;
            }
        }
        __syncthreads();                // all sm.a reads done -> buffer free

        // prefetch next A: overlaps shuffles + rs/rq + LN + stores
        if (nxt < NTILES) loadA(sm.a, nxt, t);
        COMMIT();
        if (t < 128 && nxt < NTILES) {
            int i = nxt * 128 + t;
            attnReg = g_e[i] / (g_segsum[bidx[i]] + SM_EPS);
        }

        #pragma unroll
        for (int off = 1; off <= 2; off <<= 1) {
            #pragma unroll
            for (int mt = 0; mt < 2; mt++)
                #pragma unroll
                for (int h = 0; h < 2; h++) {
                    rsum[mt][h] += __shfl_xor_sync(0xFFFFFFFFu, rsum[mt][h], off);
                    rsq[mt][h]  += __shfl_xor_sync(0xFFFFFFFFu, rsq[mt][h], off);
                }
        }
        if (tig == 0) {
            #pragma unroll
            for (int mt = 0; mt < 2; mt++)
                #pragma unroll
                for (int h = 0; h < 2; h++) {
                    int row = wm * 32 + mt * 16 + h * 8 + g;
                    sm.rs[wn][row] = rsum[mt][h];
                    sm.rq[wn][row] = rsq[mt][h];
                }
        }
        __syncthreads();                // rs/rq visible

        // ---- LN normalize + store
        #pragma unroll
        for (int mt = 0; mt < 2; mt++) {
            #pragma unroll
            for (int h = 0; h < 2; h++) {
                int row = wm * 32 + mt * 16 + h * 8 + g;
                float ts = 0.f, tq = 0.f;
                #pragma unroll
                for (int j = 0; j < 8; j++) { ts += sm.rs[j][row]; tq += sm.rq[j][row]; }
                float mu = ts * (1.f / HIDDEN);
                float var = tq * (1.f / HIDDEN) - mu * mu;
                float rstd = rsqrtf(var + LN_EPS);
                #pragma unroll
                for (int nt = 0; nt < 4; nt++) {
                    int c0 = wn * 32 + nt * 8 + 2 * tig;
                    float v0 = acc[mt][nt][h * 2 + 0];
                    float v1 = acc[mt][nt][h * 2 + 1];
                    float y0 = fmaf((v0 - mu) * rstd, sm.gm[c0],     sm.bt[c0]);
                    float y1 = fmaf((v1 - mu) * rstd, sm.gm[c0 + 1], sm.bt[c0 + 1]);
                    *(float2*)&out[(size_t)(rb + row) * HIDDEN + c0] = make_float2(y0, y1);
                }
            }
        }
        // no barrier: next iter's WAITG(0) + __syncthreads orders A reuse
    }
}

// ---------------- host ----------------
extern "C" void kernel_launch(void* const* d_in, const int* in_sizes, int n_in,
                              void* d_out, int out_size) {
    const float* drug  = (const float*)d_in[0];
    const float* prot  = (const float*)d_in[1];
    const int*   bidx  = (const int*)d_in[2];
    const float* Wq    = (const float*)d_in[3];
    const float* bq    = (const float*)d_in[4];
    const float* Wk    = (const float*)d_in[5];
    const float* bk    = (const float*)d_in[6];
    const float* Wv    = (const float*)d_in[7];
    const float* bv    = (const float*)d_in[8];
    const float* gamma = (const float*)d_in[9];
    const float* beta  = (const float*)d_in[10];

    float* out = (float*)d_out;
    float* attn_out = (out_size >= (int)((size_t)N_ATOMS * HIDDEN + N_ATOMS))
                        ? out + (size_t)N_ATOMS * HIDDEN : nullptr;

    cudaFuncSetAttribute(k_main, cudaFuncAttributeMaxDynamicSharedMemorySize,
                         (int)sizeof(Sm));

    k_pre <<<41, 256>>>(Wq, bq, Wk, bk, Wv);               // launch 0
    k_u   <<<BATCH / 16, 256>>>(prot);                     // launch 1
    k_dots<<<N_ATOMS / 16, 256>>>(drug, bidx);             // launch 2
    k_main<<<NCTAS, 1024, sizeof(Sm)>>>(bv, gamma, beta, bidx, out, attn_out); // launch 3
}

// round 16
// speedup vs baseline: 1.1137x; 1.1137x over previous
#include <cuda_runtime.h>
#include <cuda_fp16.h>
#include <cstdint>
#include <cstddef>

#define N_ATOMS 262144
#define BATCH   4096
#define HIDDEN  256
#define SCALE   0.125f
#define LN_EPS  1e-5f
#define SM_EPS  1e-16f

#define NTILES  (N_ATOMS / 128)     // 2048 tiles of 128 rows
#define NCTAS   148
#define APITCH  264                 // halves; 528B row = 4 banks mod 32
#define BPITCH  72                  // halves; 144B row = 4 banks mod 32
#define BCHUNKB (256 * BPITCH * 2)  // 36864 bytes per k64 chunk

// ---------------- scratch (device globals, no allocation) ----------------
__device__ float    g_A[HIDDEN * HIDDEN];   // A = Wq @ Wk^T
__device__ float    g_dvec[HIDDEN];
__device__ float    g_vq[HIDDEN];
__device__ float    g_cconst[1];
__device__ float    g_U[BATCH * HIDDEN];
__device__ float    g_c[BATCH];
__device__ float    g_e[N_ATOMS];           // exp(dots) directly (no max pass)
__device__ float    g_segsum[BATCH];
__device__ __half   g_WvT16[HIDDEN * HIDDEN];           // WvT16[n][k] = fp16(Wv[k][n])
__device__ __half   g_drug16[(size_t)N_ATOMS * HIDDEN]; // fp16 copy of drug

// ---------------- K0: A = Wq @ Wk^T, vq/dvec/cconst, segsum zero, Wv transpose
__global__ void k_pre(const float* __restrict__ Wq, const float* __restrict__ bq,
                      const float* __restrict__ Wk, const float* __restrict__ bk,
                      const float* __restrict__ Wv) {
    int t = threadIdx.x;
    if (blockIdx.x < 32) {
        __shared__ float wq[8][HIDDEN];
        int k0 = blockIdx.x * 8;
        #pragma unroll
        for (int e = 0; e < 8; e++) wq[e][t] = Wq[(k0 + e) * HIDDEN + t];
        __syncthreads();
        float acc[8];
        #pragma unroll
        for (int r = 0; r < 8; r++) acc[r] = 0.f;
        for (int j = 0; j < HIDDEN; j++) {
            float w = __ldg(&Wk[t * HIDDEN + j]);
            #pragma unroll
            for (int r = 0; r < 8; r++) acc[r] += wq[r][j] * w;
        }
        #pragma unroll
        for (int r = 0; r < 8; r++) g_A[(k0 + r) * HIDDEN + t] = acc[r];
    } else if (blockIdx.x == 32) {
        for (int i = t; i < BATCH; i += 256) g_segsum[i] = 0.f;
        __shared__ float bqs[HIDDEN], bks[HIDDEN];
        bqs[t] = bq[t]; bks[t] = bk[t];
        __syncthreads();
        float v = 0.f, d = 0.f;
        for (int j = 0; j < HIDDEN; j++) {
            v += __ldg(&Wq[t * HIDDEN + j]) * bks[j];
            d += __ldg(&Wk[t * HIDDEN + j]) * bqs[j];
        }
        g_vq[t] = v; g_dvec[t] = d;
        if (t == 0) {
            float c = 0.f;
            for (int j = 0; j < HIDDEN; j++) c += bqs[j] * bks[j];
            g_cconst[0] = c;
        }
    } else {
        __shared__ float ts[32][33];
        int n0 = (blockIdx.x - 33) * 32;
        int tx = t & 31, ty = t >> 5;              // 32 x 8
        for (int kb = 0; kb < 8; kb++) {
            int k0 = kb * 32;
            #pragma unroll
            for (int j = 0; j < 32; j += 8)
                ts[ty + j][tx] = Wv[(size_t)(k0 + ty + j) * HIDDEN + n0 + tx];
            __syncthreads();
            #pragma unroll
            for (int j = 0; j < 32; j += 8)
                g_WvT16[(size_t)(n0 + ty + j) * HIDDEN + k0 + tx] =
                    __float2half_rn(ts[tx][ty + j]);
            __syncthreads();
        }
    }
}

// ---------------- K1: U = protein @ A + d ; c = protein @ vq + cc ----------------
__global__ void k_u(const float* __restrict__ P) {
    __shared__ float ps[HIDDEN][16];
    __shared__ float vqs[HIDDEN];
    int t = threadIdx.x;
    int b0 = blockIdx.x * 16;
    #pragma unroll
    for (int e = 0; e < 16; e++) ps[t][e] = P[(b0 + e) * HIDDEN + t];
    vqs[t] = g_vq[t];
    __syncthreads();
    float acc[16];
    #pragma unroll
    for (int r = 0; r < 16; r++) acc[r] = 0.f;
    for (int k = 0; k < HIDDEN; k++) {
        float a = g_A[k * HIDDEN + t];
        const float4* p4 = (const float4*)ps[k];
        float4 x0 = p4[0], x1 = p4[1], x2 = p4[2], x3 = p4[3];
        acc[0]  += x0.x * a; acc[1]  += x0.y * a; acc[2]  += x0.z * a; acc[3]  += x0.w * a;
        acc[4]  += x1.x * a; acc[5]  += x1.y * a; acc[6]  += x1.z * a; acc[7]  += x1.w * a;
        acc[8]  += x2.x * a; acc[9]  += x2.y * a; acc[10] += x2.z * a; acc[11] += x2.w * a;
        acc[12] += x3.x * a; acc[13] += x3.y * a; acc[14] += x3.z * a; acc[15] += x3.w * a;
    }
    float dv = g_dvec[t];
    #pragma unroll
    for (int r = 0; r < 16; r++) g_U[(b0 + r) * HIDDEN + t] = acc[r] + dv;
    if (t < 16) {
        float s = 0.f;
        for (int k = 0; k < HIDDEN; k++) s += ps[k][t] * vqs[k];
        g_c[b0 + t] = s + g_cconst[0];
    }
}

// ---------------- K2: dots -> exp -> segment sum + drug->fp16 (4 atoms/warp) --
__device__ __forceinline__ unsigned pack2(float a, float b) {
    __half2 h = __float22half2_rn(make_float2(a, b));
    return *(unsigned*)&h;
}
__device__ __forceinline__ void stcs4(void* p, uint4 v) {
    asm volatile("st.global.cs.v4.b32 [%0], {%1,%2,%3,%4};"
        :: "l"(p), "r"(v.x), "r"(v.y), "r"(v.z), "r"(v.w) : "memory");
}

__global__ void k_dots(const float* __restrict__ drug, const int* __restrict__ bidx) {
    int warp = threadIdx.x >> 5, lane = threadIdx.x & 31;
    int i0 = (blockIdx.x * 8 + warp) * 4;

    int b[4];
    #pragma unroll
    for (int j = 0; j < 4; j++) b[j] = __ldg(&bidx[i0 + j]);

    float4 x[8], y[8];
    #pragma unroll
    for (int j = 0; j < 4; j++) {
        const float4* dr = (const float4*)(drug + (size_t)(i0 + j) * HIDDEN);
        x[2 * j]     = __ldg(&dr[lane * 2]);
        x[2 * j + 1] = __ldg(&dr[lane * 2 + 1]);
    }
    #pragma unroll
    for (int j = 0; j < 4; j++) {
        const float4* ur = (const float4*)(g_U + (size_t)b[j] * HIDDEN);
        y[2 * j]     = __ldg(&ur[lane * 2]);
        y[2 * j + 1] = __ldg(&ur[lane * 2 + 1]);
    }

    // fp16 copy (streaming stores)
    #pragma unroll
    for (int j = 0; j < 4; j++) {
        uint4 p = make_uint4(pack2(x[2*j].x, x[2*j].y),   pack2(x[2*j].z, x[2*j].w),
                             pack2(x[2*j+1].x, x[2*j+1].y), pack2(x[2*j+1].z, x[2*j+1].w));
        stcs4(g_drug16 + (size_t)(i0 + j) * HIDDEN + lane * 8, p);
    }

    float s[4];
    #pragma unroll
    for (int j = 0; j < 4; j++) {
        float4 a0 = x[2*j], a1 = x[2*j+1], c0 = y[2*j], c1 = y[2*j+1];
        s[j] = a0.x*c0.x + a0.y*c0.y + a0.z*c0.z + a0.w*c0.w
             + a1.x*c1.x + a1.y*c1.y + a1.z*c1.z + a1.w*c1.w;
    }
    #pragma unroll
    for (int off = 16; off > 0; off >>= 1) {
        #pragma unroll
        for (int j = 0; j < 4; j++) s[j] += __shfl_xor_sync(0xFFFFFFFFu, s[j], off);
    }
    if (lane == 0) {
        float e[4];
        #pragma unroll
        for (int j = 0; j < 4; j++) e[j] = expf((s[j] + g_c[b[j]]) * SCALE);
        float4 ev = make_float4(e[0], e[1], e[2], e[3]);
        stcs4(g_e + i0, *(uint4*)&ev);
        if (b[0] == b[3]) {              // sorted => all four equal
            atomicAdd(&g_segsum[b[0]], e[0] + e[1] + e[2] + e[3]);
        } else {
            #pragma unroll
            for (int j = 0; j < 4; j++) atomicAdd(&g_segsum[b[j]], e[j]);
        }
    }
}

// ---------------- K3: persistent fp16-mma V-GEMM (R11 + barrier diet) --------
// grid=148, 512 threads, M=128 tiles, B (147.5KB) resident, A single-buffered.
// vs R11: attn staged for the NEXT tile during the epilogue (tile top is just
// WAITG+sync), and out stores are streaming (.cs). 2 barriers per tile.

struct alignas(16) Sm {
    __half a[128 * APITCH];            //  67,584 B
    __half b[4][256 * BPITCH];         // 147,456 B
    float  attn[128];
    float  bvv[HIDDEN], gm[HIDDEN], bt[HIDDEN];
    float  rs[4][128], rq[4][128];
};

__device__ __forceinline__ void cp16(void* s, const void* g) {
    unsigned sa = (unsigned)__cvta_generic_to_shared(s);
    asm volatile("cp.async.cg.shared.global [%0], [%1], 16;" :: "r"(sa), "l"(g));
}
__device__ __forceinline__ void ldsm4(unsigned* r, unsigned addr) {
    asm volatile("ldmatrix.sync.aligned.m8n8.x4.shared.b16 {%0,%1,%2,%3}, [%4];"
        : "=r"(r[0]), "=r"(r[1]), "=r"(r[2]), "=r"(r[3]) : "r"(addr));
}
__device__ __forceinline__ void mma16(float* c, const unsigned* a, const unsigned* b) {
    asm volatile(
        "mma.sync.aligned.m16n8k16.row.col.f32.f16.f16.f32 "
        "{%0,%1,%2,%3},{%4,%5,%6,%7},{%8,%9},{%0,%1,%2,%3};"
        : "+f"(c[0]), "+f"(c[1]), "+f"(c[2]), "+f"(c[3])
        : "r"(a[0]), "r"(a[1]), "r"(a[2]), "r"(a[3]), "r"(b[0]), "r"(b[1]));
}
__device__ __forceinline__ void stcs2(void* p, float a, float b) {
    asm volatile("st.global.cs.v2.f32 [%0], {%1,%2};" :: "l"(p), "f"(a), "f"(b) : "memory");
}

__device__ __forceinline__ void loadA(__half* dst, int tile, int t) {
    const __half* src = g_drug16 + (size_t)tile * 128 * HIDDEN;
    #pragma unroll
    for (int e = 0; e < 8; e++) {
        int idx = e * 512 + t;
        int r = idx >> 5, j = idx & 31;
        cp16(dst + r * APITCH + j * 8, src + r * HIDDEN + j * 8);
    }
}
__device__ __forceinline__ void loadB(__half* dst, int c, int t) {
    const __half* src = g_WvT16 + c * 64;
    #pragma unroll
    for (int e = 0; e < 4; e++) {
        int idx = e * 512 + t;
        int n = idx >> 3, j = idx & 7;
        cp16(dst + n * BPITCH + j * 8, src + n * HIDDEN + j * 8);
    }
}
#define COMMIT() asm volatile("cp.async.commit_group;")
#define WAITG(n) asm volatile("cp.async.wait_group %0;" :: "n"(n) : "memory")

__global__ void __launch_bounds__(512, 1) k_main(
    const float* __restrict__ bv, const float* __restrict__ gamma,
    const float* __restrict__ beta, const int* __restrict__ bidx,
    float* __restrict__ out, float* __restrict__ attn_out)
{
    extern __shared__ char smem_raw[];
    Sm& sm = *(Sm*)smem_raw;
    int t = threadIdx.x;
    int w = t >> 5, lane = t & 31;
    int g = lane >> 2, tig = lane & 3;
    int wm = w >> 2, wn = w & 3;       // 4x4 warps: 32 rows x 64 cols each

    // one-time: B resident + first A + constants + stage attn(tile0)
    int tl = blockIdx.x;
    #pragma unroll
    for (int c = 0; c < 4; c++) loadB(sm.b[c], c, t);
    loadA(sm.a, tl, t);
    COMMIT();
    if (t < 256) { sm.bvv[t] = bv[t]; sm.gm[t] = gamma[t]; sm.bt[t] = beta[t]; }
    if (t < 128) {
        int i = tl * 128 + t;
        float a = g_e[i] / (g_segsum[bidx[i]] + SM_EPS);
        sm.attn[t] = a;
        if (attn_out) attn_out[i] = a;
    }

    unsigned aBase = (unsigned)__cvta_generic_to_shared(sm.a);
    unsigned bBase = (unsigned)__cvta_generic_to_shared(sm.b[0]);
    unsigned aLane = aBase + (unsigned)((wm * 32 + (lane & 15)) * APITCH * 2
                                        + ((lane >> 4) << 3) * 2);
    unsigned bRow  = bBase + (unsigned)((wn * 64 + ((lane >> 4) << 3) + (lane & 7)) * BPITCH * 2)
                   + (unsigned)((((lane >> 3) & 1) << 3) * 2);

    for (; tl < NTILES; tl += NCTAS) {
        int rb = tl * 128;
        int nxt = tl + NCTAS;

        WAITG(0);                       // current A complete
        __syncthreads();                // A + attn (staged last iter) visible

        // ---- mma burst
        float acc[2][8][4];
        #pragma unroll
        for (int mt = 0; mt < 2; mt++)
            #pragma unroll
            for (int nt = 0; nt < 8; nt++)
                #pragma unroll
                for (int q = 0; q < 4; q++) acc[mt][nt][q] = 0.f;

        #pragma unroll
        for (int k16 = 0; k16 < 16; k16++) {
            unsigned a0[4], a1[4];
            ldsm4(a0, aLane + (unsigned)(k16 * 32));
            ldsm4(a1, aLane + (unsigned)(16 * APITCH * 2 + k16 * 32));
            unsigned bC = bRow + (unsigned)((k16 >> 2) * BCHUNKB + (k16 & 3) * 32);
            #pragma unroll
            for (int p = 0; p < 4; p++) {
                unsigned bq[4];
                ldsm4(bq, bC + (unsigned)(p * 16 * BPITCH * 2));
                mma16(acc[0][2 * p],     a0, &bq[0]);
                mma16(acc[1][2 * p],     a1, &bq[0]);
                mma16(acc[0][2 * p + 1], a0, &bq[2]);
                mma16(acc[1][2 * p + 1], a1, &bq[2]);
            }
        }

        // ---- fold: v = attn*(acc+bv) + residual(sm.a) ; warp-local stats
        float rsum[2][2], rsq[2][2];
        #pragma unroll
        for (int mt = 0; mt < 2; mt++) { rsum[mt][0] = rsum[mt][1] = 0.f;
                                         rsq[mt][0] = rsq[mt][1] = 0.f; }
        #pragma unroll
        for (int mt = 0; mt < 2; mt++) {
            int r0 = wm * 32 + mt * 16 + g, r1 = r0 + 8;
            float a0 = sm.attn[r0], a1 = sm.attn[r1];
            #pragma unroll
            for (int nt = 0; nt < 8; nt++) {
                int c0 = wn * 64 + nt * 8 + 2 * tig;
                float2 q0 = __half22float2(*(const __half2*)&sm.a[r0 * APITCH + c0]);
                float2 q1 = __half22float2(*(const __half2*)&sm.a[r1 * APITCH + c0]);
                float bv0 = sm.bvv[c0], bv1 = sm.bvv[c0 + 1];
                float v0 = fmaf(a0, acc[mt][nt][0] + bv0, q0.x);
                float v1 = fmaf(a0, acc[mt][nt][1] + bv1, q0.y);
                float v2 = fmaf(a1, acc[mt][nt][2] + bv0, q1.x);
                float v3 = fmaf(a1, acc[mt][nt][3] + bv1, q1.y);
                acc[mt][nt][0] = v0; acc[mt][nt][1] = v1;
                acc[mt][nt][2] = v2; acc[mt][nt][3] = v3;
                rsum[mt][0] += v0 + v1;  rsq[mt][0] += v0 * v0 + v1 * v1;
                rsum[mt][1] += v2 + v3;  rsq[mt][1] += v2 * v2 + v3 * v3;
            }
        }
        #pragma unroll
        for (int off = 1; off <= 2; off <<= 1) {
            #pragma unroll
            for (int mt = 0; mt < 2; mt++)
                #pragma unroll
                for (int h = 0; h < 2; h++) {
                    rsum[mt][h] += __shfl_xor_sync(0xFFFFFFFFu, rsum[mt][h], off);
                    rsq[mt][h]  += __shfl_xor_sync(0xFFFFFFFFu, rsq[mt][h], off);
                }
        }
        if (tig == 0) {
            #pragma unroll
            for (int mt = 0; mt < 2; mt++)
                #pragma unroll
                for (int h = 0; h < 2; h++) {
                    int row = wm * 32 + mt * 16 + h * 8 + g;
                    sm.rs[wn][row] = rsum[mt][h];
                    sm.rq[wn][row] = rsq[mt][h];
                }
        }
        __syncthreads();                // sm.a free + rs/rq visible + attn free

        // prefetch next A + stage next attn (overlap LN + stores)
        if (nxt < NTILES) loadA(sm.a, nxt, t);
        COMMIT();
        if (t < 128 && nxt < NTILES) {
            int i = nxt * 128 + t;
            float a = g_e[i] / (g_segsum[bidx[i]] + SM_EPS);
            sm.attn[t] = a;
            if (attn_out) attn_out[i] = a;
        }

        // ---- LN normalize + streaming store
        #pragma unroll
        for (int mt = 0; mt < 2; mt++) {
            #pragma unroll
            for (int h = 0; h < 2; h++) {
                int row = wm * 32 + mt * 16 + h * 8 + g;
                float ts = sm.rs[0][row] + sm.rs[1][row] + sm.rs[2][row] + sm.rs[3][row];
                float tq = sm.rq[0][row] + sm.rq[1][row] + sm.rq[2][row] + sm.rq[3][row];
                float mu = ts * (1.f / HIDDEN);
                float var = tq * (1.f / HIDDEN) - mu * mu;
                float rstd = rsqrtf(var + LN_EPS);
                #pragma unroll
                for (int nt = 0; nt < 8; nt++) {
                    int c0 = wn * 64 + nt * 8 + 2 * tig;
                    float v0 = acc[mt][nt][h * 2 + 0];
                    float v1 = acc[mt][nt][h * 2 + 1];
                    float y0 = fmaf((v0 - mu) * rstd, sm.gm[c0],     sm.bt[c0]);
                    float y1 = fmaf((v1 - mu) * rstd, sm.gm[c0 + 1], sm.bt[c0 + 1]);
                    stcs2(&out[(size_t)(rb + row) * HIDDEN + c0], y0, y1);
                }
            }
        }
        // no barrier: next iter's WAITG(0) + __syncthreads orders A reuse
    }
}

// ---------------- host ----------------
extern "C" void kernel_launch(void* const* d_in, const int* in_sizes, int n_in,
                              void* d_out, int out_size) {
    const float* drug  = (const float*)d_in[0];
    const float* prot  = (const float*)d_in[1];
    const int*   bidx  = (const int*)d_in[2];
    const float* Wq    = (const float*)d_in[3];
    const float* bq    = (const float*)d_in[4];
    const float* Wk    = (const float*)d_in[5];
    const float* bk    = (const float*)d_in[6];
    const float* Wv    = (const float*)d_in[7];
    const float* bv    = (const float*)d_in[8];
    const float* gamma = (const float*)d_in[9];
    const float* beta  = (const float*)d_in[10];

    float* out = (float*)d_out;
    float* attn_out = (out_size >= (int)((size_t)N_ATOMS * HIDDEN + N_ATOMS))
                        ? out + (size_t)N_ATOMS * HIDDEN : nullptr;

    cudaFuncSetAttribute(k_main, cudaFuncAttributeMaxDynamicSharedMemorySize,
                         (int)sizeof(Sm));

    k_pre <<<41, 256>>>(Wq, bq, Wk, bk, Wv);               // launch 0
    k_u   <<<BATCH / 16, 256>>>(prot);                     // launch 1
    k_dots<<<N_ATOMS / 32, 256>>>(drug, bidx);             // launch 2
    k_main<<<NCTAS, 512, sizeof(Sm)>>>(bv, gamma, beta, bidx, out, attn_out);  // launch 3
}